// round 16
// baseline (speedup 1.0000x reference)
#include <cuda_runtime.h>

// SidNetLayer: N=50000, E=600000 per signed adjacency, D=128, K=10, C=0.15.
//   new_P = Ap*P + Am*M + 0.15*X
//   new_M = Am*P + Ap*M
// R16: feature-split diffusion. TWO warps per row: warp (w,h) handles
// features [64h, 64h+64) of row w with float2 gathers (256B/warp-load,
// coalesced). Per-edge body shape identical to R7 (best measured), but
// chip-wide independent load chains DOUBLE (25000 warps) — grid-level
// concurrency that ptxas cannot re-serialize (R8-R12 showed register/async
// level MLP attempts all fail). Build kernels unchanged from R15.

#define NMAX  50000
#define EMAX  600000
#define DD    128
#define DV2   64          // D/2 float2 per row
#define KITER 10
#define CREST 0.15f

// ---------------- persistent device scratch --------------------------------
__device__ int  g_cnt[NMAX];      // zero at entry; scatter_k restores invariant
__device__ int  g_start[NMAX];    // exclusive row starts
__device__ int  g_cur[NMAX];      // scatter cursors (init = start)
__device__ int2 g_cv[2 * EMAX];   // packed {col | bit31 sign, val bits}
__device__ float g_PM[2][(size_t)2 * NMAX * DD];  // ping-pong, P then M

// ---------------- CSR build (3 launches, R15 versions) -----------------------
__global__ void hist_k(const int* __restrict__ rp, const int* __restrict__ rm, int E) {
    int i = (blockIdx.x * blockDim.x + threadIdx.x) * 4;
    if (i + 4 <= E) {
        int4 a = *(const int4*)(rp + i);
        int4 b = *(const int4*)(rm + i);
        atomicAdd(&g_cnt[a.x], 1); atomicAdd(&g_cnt[a.y], 1);
        atomicAdd(&g_cnt[a.z], 1); atomicAdd(&g_cnt[a.w], 1);
        atomicAdd(&g_cnt[b.x], 1); atomicAdd(&g_cnt[b.y], 1);
        atomicAdd(&g_cnt[b.z], 1); atomicAdd(&g_cnt[b.w], 1);
    } else {
        for (; i < E; i++) {
            atomicAdd(&g_cnt[rp[i]], 1);
            atomicAdd(&g_cnt[rm[i]], 1);
        }
    }
}

__global__ void __launch_bounds__(1024)
scan_k(int n) {
    __shared__ int warp_inc[32];
    __shared__ int warp_off[32];
    __shared__ int red[32];
    __shared__ int sprefix;

    int tid  = threadIdx.x;
    int lane = tid & 31;
    int wid  = tid >> 5;
    int gid  = blockIdx.x * 1024 + tid;

    int v = (gid < n) ? g_cnt[gid] : 0;

    int x = v;
#pragma unroll
    for (int o = 1; o < 32; o <<= 1) {
        int y = __shfl_up_sync(0xffffffffu, x, o);
        if (lane >= o) x += y;
    }
    if (lane == 31) warp_inc[wid] = x;

    int ps = 0;
    int lim = blockIdx.x * 1024;
    for (int i = tid; i < lim; i += 1024) ps += g_cnt[i];
#pragma unroll
    for (int o = 16; o > 0; o >>= 1) ps += __shfl_down_sync(0xffffffffu, ps, o);
    if (lane == 0) red[wid] = ps;
    __syncthreads();

    if (tid < 32) {
        int s = warp_inc[tid];
        int t = s;
#pragma unroll
        for (int o = 1; o < 32; o <<= 1) {
            int y = __shfl_up_sync(0xffffffffu, t, o);
            if (tid >= o) t += y;
        }
        warp_off[tid] = t - s;
        int r = red[tid];
#pragma unroll
        for (int o = 16; o > 0; o >>= 1) r += __shfl_down_sync(0xffffffffu, r, o);
        if (tid == 0) sprefix = r;
    }
    __syncthreads();

    if (gid < n) {
        int st = sprefix + warp_off[wid] + (x - v);
        g_start[gid] = st;
        g_cur[gid]   = st;
    }
}

__global__ void scatter_k(const int* __restrict__ rp, const int* __restrict__ cp,
                          const float* __restrict__ vp,
                          const int* __restrict__ rm, const int* __restrict__ cm,
                          const float* __restrict__ vm, int E, int n) {
    int t = blockIdx.x * blockDim.x + threadIdx.x;
    if (t < n) g_cnt[t] = 0;   // restore invariant for next call
    int i = t * 2;
    if (i + 2 <= E) {
        int2   r0 = *(const int2*)(rp + i);
        int2   c0 = *(const int2*)(cp + i);
        float2 v0 = *(const float2*)(vp + i);
        int2   r1 = *(const int2*)(rm + i);
        int2   c1 = *(const int2*)(cm + i);
        float2 v1 = *(const float2*)(vm + i);
        int pos;
        pos = atomicAdd(&g_cur[r0.x], 1); g_cv[pos] = make_int2(c0.x, __float_as_int(v0.x));
        pos = atomicAdd(&g_cur[r0.y], 1); g_cv[pos] = make_int2(c0.y, __float_as_int(v0.y));
        pos = atomicAdd(&g_cur[r1.x], 1); g_cv[pos] = make_int2(c1.x | 0x80000000, __float_as_int(v1.x));
        pos = atomicAdd(&g_cur[r1.y], 1); g_cv[pos] = make_int2(c1.y | 0x80000000, __float_as_int(v1.y));
    } else {
        for (; i < E; i++) {
            int pos = atomicAdd(&g_cur[rp[i]], 1);
            g_cv[pos] = make_int2(cp[i], __float_as_int(vp[i]));
            pos = atomicAdd(&g_cur[rm[i]], 1);
            g_cv[pos] = make_int2(cm[i] | 0x80000000, __float_as_int(vm[i]));
        }
    }
}

// ---------------- fused diffusion iteration (feature-split) ------------------
// Warp (w, h): row w, features [64h, 64h+64). float2 gathers.
//   flag ? (accP += v*M[c], accM += v*P[c]) : (accP += v*P[c], accM += v*M[c])
__global__ void __launch_bounds__(128)
diffuse_k(const float2* __restrict__ Ps, const float2* __restrict__ Ms,
          const float2* __restrict__ X2,
          float2* __restrict__ Pd, float2* __restrict__ Md,
          int n, int Etot) {
    int gw = (blockIdx.x * blockDim.x + threadIdx.x) >> 5;
    unsigned lane = threadIdx.x & 31;
    int w = gw >> 1;
    if (w >= n) return;
    unsigned fo = ((unsigned)(gw & 1)) * 32 + lane;   // float2 index in row

    float2 x = __ldg(&X2[(unsigned)w * DV2 + fo]);
    float aP0 = CREST * x.x, aP1 = CREST * x.y;
    float aM0 = 0.f, aM1 = 0.f;

    int s = g_start[w];
    int e = (w + 1 < n) ? g_start[w + 1] : Etot;

#pragma unroll 4
    for (int j = s; j < e; j++) {
        // all lanes load the same 8B record: broadcast, 1 wavefront, L1-hot
        int2 cv = __ldg(&g_cv[j]);
        int   cj = cv.x;
        float vj = __int_as_float(cv.y);
        unsigned off = (unsigned)(cj & 0x7fffffff) * DV2 + fo;
        const float2* A = (cj < 0) ? Ms : Ps;   // feeds accP
        const float2* B = (cj < 0) ? Ps : Ms;   // feeds accM
        float2 a = __ldg(&A[off]);
        float2 b = __ldg(&B[off]);
        aP0 += vj * a.x; aP1 += vj * a.y;
        aM0 += vj * b.x; aM1 += vj * b.y;
    }

    Pd[(unsigned)w * DV2 + fo] = make_float2(aP0, aP1);
    Md[(unsigned)w * DV2 + fo] = make_float2(aM0, aM1);
}

// ---------------- launch -----------------------------------------------------
extern "C" void kernel_launch(void* const* d_in, const int* in_sizes, int n_in,
                              void* d_out, int out_size) {
    const int*   rp = (const int*)d_in[0];
    const int*   cp = (const int*)d_in[1];
    const float* vp = (const float*)d_in[2];
    const int*   rm = (const int*)d_in[3];
    const int*   cm = (const int*)d_in[4];
    const float* vm = (const float*)d_in[5];
    const float* X  = (const float*)d_in[6];
    const float* M0 = (const float*)d_in[7];

    int E = in_sizes[0];
    int n = in_sizes[6] / DD;
    int Etot = 2 * E;

    int histThreads = (E + 3) / 4;
    hist_k<<<(histThreads + 255) / 256, 256>>>(rp, rm, E);
    scan_k<<<(n + 1023) / 1024, 1024>>>(n);
    int scatThreads = (E + 1) / 2;
    int scatGridMin = (n + 255) / 256;
    int scatGrid = (scatThreads + 255) / 256;
    if (scatGrid < scatGridMin) scatGrid = scatGridMin;
    scatter_k<<<scatGrid, 256>>>(rp, cp, vp, rm, cm, vm, E, n);

    float* gPM = nullptr;
    cudaGetSymbolAddress((void**)&gPM, g_PM);

    const float* Ps = X;
    const float* Ms = M0;
    int nw = 2 * n;                       // two warps per row
    int grid = (nw + 3) / 4;              // 4 warps / 128-thread block

    for (int it = 0; it < KITER; ++it) {
        float *Pd, *Md;
        if (it == KITER - 1) {
            Pd = (float*)d_out;
            Md = (float*)d_out + (size_t)n * DD;
        } else {
            int b = it & 1;
            float* basep = gPM + (size_t)b * 2 * NMAX * DD;
            Pd = basep;
            Md = basep + (size_t)n * DD;
        }
        diffuse_k<<<grid, 128>>>((const float2*)Ps, (const float2*)Ms,
                                 (const float2*)X, (float2*)Pd, (float2*)Md,
                                 n, Etot);
        Ps = Pd;
        Ms = Md;
    }
}

// round 17
// speedup vs baseline: 1.0681x; 1.0681x over previous
#include <cuda_runtime.h>

// SidNetLayer: N=50000, E=600000 per signed adjacency, D=128, K=10, C=0.15.
//   new_P = Ap*P + Am*M + 0.15*X
//   new_M = Am*P + Ap*M
// R17 = champion R7/R15 diffuse body + L2 residency hints:
//   - __ldcs on edge records (streamed once per iter -> evict-first)
//   - __stcs on output stores (no reuse within kernel -> evict-first)
//   - X pre-scaled by C once (tilde buffer), inner loop drops 4 FMULs
// Rationale (R15 ncu): 112MB DRAM/iter vs 51MB writes => the 51MB source
// set is evicted every iteration by dest-allocate + streams; hints keep
// gathered source rows resident so tail gathers hit L2 (234cyc) not DRAM
// (577cyc). Eight structural variants (R8-R14,R16) all measured worse than
// this body — it stays byte-identical otherwise.

#define NMAX  50000
#define EMAX  600000
#define DD    128
#define DV    32          // D/4 float4 per row
#define KITER 10
#define CREST 0.15f

// ---------------- persistent device scratch --------------------------------
__device__ int  g_cnt[NMAX];      // zero at entry; scatter_k restores invariant
__device__ int  g_start[NMAX];    // exclusive row starts
__device__ int  g_cur[NMAX];      // scatter cursors (init = start)
__device__ int2 g_cv[2 * EMAX];   // packed {col | bit31 sign, val bits}
__device__ float g_PM[2][(size_t)2 * NMAX * DD];  // ping-pong, P then M
__device__ float g_tX[(size_t)NMAX * DD];         // C * X (restart term)

// ---------------- CSR build (3 launches) ------------------------------------
__global__ void hist_k(const int* __restrict__ rp, const int* __restrict__ rm, int E) {
    int i = (blockIdx.x * blockDim.x + threadIdx.x) * 4;
    if (i + 4 <= E) {
        int4 a = *(const int4*)(rp + i);
        int4 b = *(const int4*)(rm + i);
        atomicAdd(&g_cnt[a.x], 1); atomicAdd(&g_cnt[a.y], 1);
        atomicAdd(&g_cnt[a.z], 1); atomicAdd(&g_cnt[a.w], 1);
        atomicAdd(&g_cnt[b.x], 1); atomicAdd(&g_cnt[b.y], 1);
        atomicAdd(&g_cnt[b.z], 1); atomicAdd(&g_cnt[b.w], 1);
    } else {
        for (; i < E; i++) {
            atomicAdd(&g_cnt[rp[i]], 1);
            atomicAdd(&g_cnt[rm[i]], 1);
        }
    }
}

__global__ void __launch_bounds__(1024)
scan_k(int n) {
    __shared__ int warp_inc[32];
    __shared__ int warp_off[32];
    __shared__ int red[32];
    __shared__ int sprefix;

    int tid  = threadIdx.x;
    int lane = tid & 31;
    int wid  = tid >> 5;
    int gid  = blockIdx.x * 1024 + tid;

    int v = (gid < n) ? g_cnt[gid] : 0;

    int x = v;
#pragma unroll
    for (int o = 1; o < 32; o <<= 1) {
        int y = __shfl_up_sync(0xffffffffu, x, o);
        if (lane >= o) x += y;
    }
    if (lane == 31) warp_inc[wid] = x;

    int ps = 0;
    int lim = blockIdx.x * 1024;
    for (int i = tid; i < lim; i += 1024) ps += g_cnt[i];
#pragma unroll
    for (int o = 16; o > 0; o >>= 1) ps += __shfl_down_sync(0xffffffffu, ps, o);
    if (lane == 0) red[wid] = ps;
    __syncthreads();

    if (tid < 32) {
        int s = warp_inc[tid];
        int t = s;
#pragma unroll
        for (int o = 1; o < 32; o <<= 1) {
            int y = __shfl_up_sync(0xffffffffu, t, o);
            if (tid >= o) t += y;
        }
        warp_off[tid] = t - s;
        int r = red[tid];
#pragma unroll
        for (int o = 16; o > 0; o >>= 1) r += __shfl_down_sync(0xffffffffu, r, o);
        if (tid == 0) sprefix = r;
    }
    __syncthreads();

    if (gid < n) {
        int st = sprefix + warp_off[wid] + (x - v);
        g_start[gid] = st;
        g_cur[gid]   = st;
    }
}

// also pre-scales X into g_tX (C * X), fused into the scatter pass
__global__ void scatter_k(const int* __restrict__ rp, const int* __restrict__ cp,
                          const float* __restrict__ vp,
                          const int* __restrict__ rm, const int* __restrict__ cm,
                          const float* __restrict__ vm,
                          const float4* __restrict__ X4, int E, int n) {
    int t = blockIdx.x * blockDim.x + threadIdx.x;
    if (t < n) g_cnt[t] = 0;   // restore invariant for next call
    // pre-scale X: n*DD floats = n*32 float4; grid covers E/2 >= n*32? E/2=300000,
    // n*32=1600000 -> stride loop
    for (int xi = t; xi < n * DV; xi += gridDim.x * blockDim.x) {
        float4 xv = __ldg(&X4[xi]);
        ((float4*)g_tX)[xi] = make_float4(CREST * xv.x, CREST * xv.y,
                                          CREST * xv.z, CREST * xv.w);
    }
    int i = t * 2;
    if (i + 2 <= E) {
        int2   r0 = *(const int2*)(rp + i);
        int2   c0 = *(const int2*)(cp + i);
        float2 v0 = *(const float2*)(vp + i);
        int2   r1 = *(const int2*)(rm + i);
        int2   c1 = *(const int2*)(cm + i);
        float2 v1 = *(const float2*)(vm + i);
        int pos;
        pos = atomicAdd(&g_cur[r0.x], 1); g_cv[pos] = make_int2(c0.x, __float_as_int(v0.x));
        pos = atomicAdd(&g_cur[r0.y], 1); g_cv[pos] = make_int2(c0.y, __float_as_int(v0.y));
        pos = atomicAdd(&g_cur[r1.x], 1); g_cv[pos] = make_int2(c1.x | 0x80000000, __float_as_int(v1.x));
        pos = atomicAdd(&g_cur[r1.y], 1); g_cv[pos] = make_int2(c1.y | 0x80000000, __float_as_int(v1.y));
    } else {
        for (; i < E; i++) {
            int pos = atomicAdd(&g_cur[rp[i]], 1);
            g_cv[pos] = make_int2(cp[i], __float_as_int(vp[i]));
            pos = atomicAdd(&g_cur[rm[i]], 1);
            g_cv[pos] = make_int2(cm[i] | 0x80000000, __float_as_int(vm[i]));
        }
    }
}

// ---------------- fused diffusion iteration (champion body + hints) ----------
__global__ void __launch_bounds__(128)
diffuse_k(const float4* __restrict__ Ps, const float4* __restrict__ Ms,
          const float4* __restrict__ tX4,
          float4* __restrict__ Pd, float4* __restrict__ Md,
          int n, int Etot) {
    int w = (blockIdx.x * blockDim.x + threadIdx.x) >> 5;
    unsigned lane = threadIdx.x & 31;
    if (w >= n) return;

    float4 x = __ldg(&tX4[(unsigned)w * DV + lane]);   // already C-scaled
    float aP0 = x.x, aP1 = x.y, aP2 = x.z, aP3 = x.w;
    float aM0 = 0.f, aM1 = 0.f, aM2 = 0.f, aM3 = 0.f;

    int s = g_start[w];
    int e = (w + 1 < n) ? g_start[w + 1] : Etot;

#pragma unroll 4
    for (int j = s; j < e; j++) {
        // record stream: read once per iteration -> evict-first hint
        int2 cv = __ldcs(&g_cv[j]);
        int   cj = cv.x;
        float vj = __int_as_float(cv.y);
        unsigned off = (unsigned)(cj & 0x7fffffff) * DV + lane;
        const float4* A = (cj < 0) ? Ms : Ps;   // feeds accP
        const float4* B = (cj < 0) ? Ps : Ms;   // feeds accM
        float4 a = __ldg(&A[off]);
        float4 b = __ldg(&B[off]);
        aP0 += vj * a.x; aP1 += vj * a.y; aP2 += vj * a.z; aP3 += vj * a.w;
        aM0 += vj * b.x; aM1 += vj * b.y; aM2 += vj * b.z; aM3 += vj * b.w;
    }

    // outputs: not re-read in this kernel -> evict-first, protect source set
    __stcs(&Pd[(unsigned)w * DV + lane], make_float4(aP0, aP1, aP2, aP3));
    __stcs(&Md[(unsigned)w * DV + lane], make_float4(aM0, aM1, aM2, aM3));
}

// ---------------- launch -----------------------------------------------------
extern "C" void kernel_launch(void* const* d_in, const int* in_sizes, int n_in,
                              void* d_out, int out_size) {
    const int*   rp = (const int*)d_in[0];
    const int*   cp = (const int*)d_in[1];
    const float* vp = (const float*)d_in[2];
    const int*   rm = (const int*)d_in[3];
    const int*   cm = (const int*)d_in[4];
    const float* vm = (const float*)d_in[5];
    const float* X  = (const float*)d_in[6];
    const float* M0 = (const float*)d_in[7];

    int E = in_sizes[0];
    int n = in_sizes[6] / DD;
    int Etot = 2 * E;

    int histThreads = (E + 3) / 4;
    hist_k<<<(histThreads + 255) / 256, 256>>>(rp, rm, E);
    scan_k<<<(n + 1023) / 1024, 1024>>>(n);
    int scatThreads = (E + 1) / 2;
    int scatGridMin = (n + 255) / 256;
    int scatGrid = (scatThreads + 255) / 256;
    if (scatGrid < scatGridMin) scatGrid = scatGridMin;
    scatter_k<<<scatGrid, 256>>>(rp, cp, vp, rm, cm, vm, (const float4*)X, E, n);

    float* gPM = nullptr;
    float* gtX = nullptr;
    cudaGetSymbolAddress((void**)&gPM, g_PM);
    cudaGetSymbolAddress((void**)&gtX, g_tX);

    const float* Ps = X;
    const float* Ms = M0;
    int grid = (n + 3) / 4;   // 4 warps / 128-thread block, 1 warp per row

    for (int it = 0; it < KITER; ++it) {
        float *Pd, *Md;
        if (it == KITER - 1) {
            Pd = (float*)d_out;
            Md = (float*)d_out + (size_t)n * DD;
        } else {
            int b = it & 1;
            float* basep = gPM + (size_t)b * 2 * NMAX * DD;
            Pd = basep;
            Md = basep + (size_t)n * DD;
        }
        diffuse_k<<<grid, 128>>>((const float4*)Ps, (const float4*)Ms,
                                 (const float4*)gtX, (float4*)Pd, (float4*)Md,
                                 n, Etot);
        Ps = Pd;
        Ms = Md;
    }
}